// round 1
// baseline (speedup 1.0000x reference)
#include <cuda_runtime.h>

// Problem constants
#define BATCH 32
#define SEQ   576
#define CH    768
#define NH    12
#define HD    64
#define MROWS (BATCH * SEQ)      // 18432
#define QKVC  (3 * CH)           // 2304
#define GRID24 24
#define BS4   4

// Scratch (allocation-free rule: __device__ globals)
__device__ float g_qkv[(size_t)MROWS * QKVC];   // (B*N, 3C) = qkv projection output
__device__ float g_att[(size_t)MROWS * CH];     // (B*N, C)  = attention output (pre-proj)

__device__ __forceinline__ int block_idx_of(int p) {
    int i = p / GRID24;
    int j = p - i * GRID24;
    return (i >> 2) * (GRID24 / BS4) + (j >> 2);   // (i/4)*6 + (j/4)
}

// ---------------------------------------------------------------------------
// SGEMM (NT): C[M,N] = A[M,K] @ B[N,K]^T + bias[N]
// A row-major MxK, B row-major NxK (both K-contiguous). 128x128x8 tile,
// 256 threads, 8x8 register blocking. All dims multiples of tile sizes here.
// ---------------------------------------------------------------------------
__global__ __launch_bounds__(256)
void sgemm_nt_bias(const float* __restrict__ A,
                   const float* __restrict__ Bm,
                   const float* __restrict__ bias,
                   float* __restrict__ Cm,
                   int Md, int Nd, int Kd)
{
    const int BM = 128, BN = 128, BK = 8, TM = 8, TN = 8;
    __shared__ float As[BK][BM];
    __shared__ float Bs[BK][BN];

    const int t  = threadIdx.x;      // 0..255
    const int tx = t & 15;           // 0..15
    const int ty = t >> 4;           // 0..15
    const int bx = blockIdx.x;
    const int by = blockIdx.y;

    const int lr = t >> 1;           // load row 0..127
    const int lc = (t & 1) << 2;     // load col {0,4}

    const float* Ag = A  + (size_t)(by * BM + lr) * Kd + lc;
    const float* Bg = Bm + (size_t)(bx * BN + lr) * Kd + lc;

    float acc[TM][TN];
#pragma unroll
    for (int i = 0; i < TM; i++)
#pragma unroll
        for (int j = 0; j < TN; j++) acc[i][j] = 0.f;

    for (int k0 = 0; k0 < Kd; k0 += BK) {
        float4 a4 = *(const float4*)(Ag + k0);
        float4 b4 = *(const float4*)(Bg + k0);
        As[lc + 0][lr] = a4.x; As[lc + 1][lr] = a4.y;
        As[lc + 2][lr] = a4.z; As[lc + 3][lr] = a4.w;
        Bs[lc + 0][lr] = b4.x; Bs[lc + 1][lr] = b4.y;
        Bs[lc + 2][lr] = b4.z; Bs[lc + 3][lr] = b4.w;
        __syncthreads();

#pragma unroll
        for (int kk = 0; kk < BK; kk++) {
            float af[TM], bf[TN];
            *(float4*)&af[0] = *(const float4*)&As[kk][ty * TM];
            *(float4*)&af[4] = *(const float4*)&As[kk][ty * TM + 4];
            *(float4*)&bf[0] = *(const float4*)&Bs[kk][tx * TN];
            *(float4*)&bf[4] = *(const float4*)&Bs[kk][tx * TN + 4];
#pragma unroll
            for (int i = 0; i < TM; i++)
#pragma unroll
                for (int j = 0; j < TN; j++)
                    acc[i][j] += af[i] * bf[j];
        }
        __syncthreads();
    }

    const int row0 = by * BM + ty * TM;
    const int col0 = bx * BN + tx * TN;
    float bj[TN];
#pragma unroll
    for (int j = 0; j < TN; j++) bj[j] = bias[col0 + j];

#pragma unroll
    for (int i = 0; i < TM; i++) {
        float* cp = Cm + (size_t)(row0 + i) * Nd + col0;
        float4 v0, v1;
        v0.x = acc[i][0] + bj[0]; v0.y = acc[i][1] + bj[1];
        v0.z = acc[i][2] + bj[2]; v0.w = acc[i][3] + bj[3];
        v1.x = acc[i][4] + bj[4]; v1.y = acc[i][5] + bj[5];
        v1.z = acc[i][6] + bj[6]; v1.w = acc[i][7] + bj[7];
        *(float4*)(cp)     = v0;
        *(float4*)(cp + 4) = v1;
    }
}

// ---------------------------------------------------------------------------
// Flash-style block-causal attention, fp32.
// One block = (qt, h, b): 192 query rows; 1 thread = 1 query row.
// q and o accumulator in registers (64+64), K/V 64-row tiles in smem,
// online softmax over 16-key chunks; fully-masked chunks skipped.
// qkv layout: row (b*576+n), cols [3C] ordered (s, h, d): q at h*64, k at
// 768 + h*64, v at 1536 + h*64.
// ---------------------------------------------------------------------------
__global__ __launch_bounds__(192, 2)
void attn_kernel(const float* __restrict__ qkv, float* __restrict__ attn_out)
{
    __shared__ float Ks[64][64];
    __shared__ float Vs[64][64];
    __shared__ int   kbi[64];
    __shared__ int   cmin[4];

    const int b   = blockIdx.z;
    const int h   = blockIdx.y;
    const int qt  = blockIdx.x;
    const int tid = threadIdx.x;        // 0..191
    const int qrow = qt * 192 + tid;    // 0..575

    const float* qptr = qkv + (size_t)(b * SEQ + qrow) * QKVC + h * HD;
    float q[HD];
#pragma unroll
    for (int d = 0; d < HD; d += 4)
        *(float4*)&q[d] = *(const float4*)(qptr + d);

    const int bq = block_idx_of(qrow);
    float m = -1e30f, l = 0.f;
    float o[HD];
#pragma unroll
    for (int d = 0; d < HD; d++) o[d] = 0.f;

    const float scale = 0.125f;   // hd^-0.5 = 1/8

    for (int kt = 0; kt < SEQ / 64; kt++) {
        const float* kbase = qkv + (size_t)(b * SEQ + kt * 64) * QKVC + CH + h * HD;
        const float* vbase = kbase + CH;
        for (int u = tid; u < 64 * 16; u += 192) {
            int r = u >> 4, c = (u & 15) << 2;
            *(float4*)&Ks[r][c] = *(const float4*)(kbase + (size_t)r * QKVC + c);
            *(float4*)&Vs[r][c] = *(const float4*)(vbase + (size_t)r * QKVC + c);
        }
        if (tid < 64) kbi[tid] = block_idx_of(kt * 64 + tid);
        if (tid < 4) {
            int mn = 1 << 30;
#pragma unroll
            for (int jj = 0; jj < 16; jj++)
                mn = min(mn, block_idx_of(kt * 64 + tid * 16 + jj));
            cmin[tid] = mn;
        }
        __syncthreads();

        for (int c = 0; c < 4; c++) {
            if (cmin[c] > bq) continue;          // entire 16-key chunk masked
            const int jb = c * 16;
            float s[16];
            float cmax = -1e30f;
#pragma unroll
            for (int j = 0; j < 16; j++) {
                if (kbi[jb + j] > bq) { s[j] = -1e30f; continue; }
                float a0 = 0.f, a1 = 0.f, a2 = 0.f, a3 = 0.f;
#pragma unroll
                for (int d = 0; d < HD; d += 4) {
                    a0 += q[d + 0] * Ks[jb + j][d + 0];
                    a1 += q[d + 1] * Ks[jb + j][d + 1];
                    a2 += q[d + 2] * Ks[jb + j][d + 2];
                    a3 += q[d + 3] * Ks[jb + j][d + 3];
                }
                float sv = ((a0 + a1) + (a2 + a3)) * scale;
                s[j] = sv;
                cmax = fmaxf(cmax, sv);
            }
            if (cmax < -1e29f) continue;

            float mnew = fmaxf(m, cmax);
            float corr = __expf(m - mnew);       // m=-1e30 -> corr underflows to 0
            l *= corr;
#pragma unroll
            for (int d = 0; d < HD; d++) o[d] *= corr;

#pragma unroll
            for (int j = 0; j < 16; j++) {
                if (s[j] < -1e29f) continue;     // masked
                float p = __expf(s[j] - mnew);
                l += p;
#pragma unroll
                for (int d = 0; d < HD; d++)
                    o[d] += p * Vs[jb + j][d];
            }
            m = mnew;
        }
        __syncthreads();
    }

    const float inv = 1.f / l;
    float* optr = attn_out + (size_t)(b * SEQ + qrow) * CH + h * HD;
#pragma unroll
    for (int d = 0; d < HD; d += 4) {
        float4 v;
        v.x = o[d + 0] * inv; v.y = o[d + 1] * inv;
        v.z = o[d + 2] * inv; v.w = o[d + 3] * inv;
        *(float4*)(optr + d) = v;
    }
}

// ---------------------------------------------------------------------------
// Launch: qkv-GEMM -> attention -> proj-GEMM (3 graph nodes)
// Inputs: x(f32 B*N*C), qkv_w(3C,C), qkv_b(3C), proj_w(C,C), proj_b(C)
// Output: f32 (B*N, C)
// ---------------------------------------------------------------------------
extern "C" void kernel_launch(void* const* d_in, const int* in_sizes, int n_in,
                              void* d_out, int out_size)
{
    const float* x      = (const float*)d_in[0];
    const float* qkv_w  = (const float*)d_in[1];
    const float* qkv_b  = (const float*)d_in[2];
    const float* proj_w = (const float*)d_in[3];
    const float* proj_b = (const float*)d_in[4];
    float* out = (float*)d_out;

    float* qkvbuf = nullptr;
    float* attbuf = nullptr;
    cudaGetSymbolAddress((void**)&qkvbuf, g_qkv);
    cudaGetSymbolAddress((void**)&attbuf, g_att);

    // 1) qkv = x @ qkv_w^T + qkv_b : (18432, 2304)
    dim3 g1(QKVC / 128, MROWS / 128);   // (18, 144)
    sgemm_nt_bias<<<g1, 256>>>(x, qkv_w, qkv_b, qkvbuf, MROWS, QKVC, CH);

    // 2) block-causal attention -> (18432, 768)
    dim3 g2(SEQ / 192, NH, BATCH);      // (3, 12, 32)
    attn_kernel<<<g2, 192>>>(qkvbuf, attbuf);

    // 3) out = att @ proj_w^T + proj_b : (18432, 768)
    dim3 g3(CH / 128, MROWS / 128);     // (6, 144)
    sgemm_nt_bias<<<g3, 256>>>(attbuf, proj_w, proj_b, out, MROWS, CH, CH);
}

// round 2
// speedup vs baseline: 2.0517x; 2.0517x over previous
#include <cuda_runtime.h>
#include <cstdint>

// Problem constants
#define BATCH 32
#define SEQ   576
#define CH    768
#define NH    12
#define HD    64
#define MROWS (BATCH * SEQ)      // 18432
#define QKVC  (3 * CH)           // 2304
#define GRID24 24
#define BS4   4

// Scratch (allocation-free rule: __device__ globals)
__device__ float g_qkv[(size_t)MROWS * QKVC];   // (B*N, 3C)
__device__ float g_att[(size_t)MROWS * CH];     // (B*N, C)

__device__ __forceinline__ int block_idx_of(int p) {
    int i = p / GRID24;
    int j = p - i * GRID24;
    return (i >> 2) * (GRID24 / BS4) + (j >> 2);
}

// ---------------------------------------------------------------------------
// cp.async helpers
// ---------------------------------------------------------------------------
__device__ __forceinline__ void cp_async16(void* smem, const void* gmem) {
    uint32_t s = (uint32_t)__cvta_generic_to_shared(smem);
    asm volatile("cp.async.cg.shared.global [%0], [%1], 16;\n" :: "r"(s), "l"(gmem));
}
__device__ __forceinline__ void cp_commit() {
    asm volatile("cp.async.commit_group;\n");
}
template<int N>
__device__ __forceinline__ void cp_wait() {
    asm volatile("cp.async.wait_group %0;\n" :: "n"(N));
}
__device__ __forceinline__ uint32_t f2tf32(float f) {
    uint32_t u;
    asm("cvt.rna.tf32.f32 %0, %1;\n" : "=r"(u) : "f"(f));
    return u;
}

// ---------------------------------------------------------------------------
// TF32 tensor-core GEMM (NT): C[M,N] = A[M,K] @ B[N,K]^T + bias[N]
// 128x128x16 block tile, 256 threads = 8 warps (4m x 2n), warp tile 32x64,
// mma.sync.m16n8k8.tf32, cp.async double buffer, padded smem (stride 20)
// for conflict-free fragment loads. Requires K % 16 == 0 (here K=768).
// ---------------------------------------------------------------------------
__global__ __launch_bounds__(256)
void tf32_gemm_nt_bias(const float* __restrict__ A,
                       const float* __restrict__ Bm,
                       const float* __restrict__ bias,
                       float* __restrict__ Cm,
                       int Md, int Nd, int Kd)
{
    const int BM = 128, BN = 128, BK = 16;
    const int LDA = 20;  // padded row stride (floats) -> conflict-free frags
    __shared__ float As[2][BM * LDA];
    __shared__ float Bs[2][BN * LDA];

    const int tid  = threadIdx.x;
    const int wid  = tid >> 5;
    const int lane = tid & 31;
    const int g    = lane >> 2;     // group id 0..7
    const int t4   = lane & 3;      // thread-in-group 0..3
    const int wm   = (wid & 3) * 32;   // warp m offset in tile
    const int wn   = (wid >> 2) * 64;  // warp n offset in tile
    const int bx = blockIdx.x, by = blockIdx.y;

    const float* Ag = A  + (size_t)(by * BM) * Kd;
    const float* Bg = Bm + (size_t)(bx * BN) * Kd;

    float acc[2][8][4];
#pragma unroll
    for (int mt = 0; mt < 2; mt++)
#pragma unroll
        for (int nt = 0; nt < 8; nt++)
#pragma unroll
            for (int r = 0; r < 4; r++) acc[mt][nt][r] = 0.f;

    const int nk = Kd / BK;

    // issue tile kt into stage s
    auto issue_tile = [&](int s, int kt) {
        const int k0 = kt * BK;
#pragma unroll
        for (int i = 0; i < 2; i++) {
            int c  = tid + (i << 8);       // 0..511
            int r  = c >> 2;               // row 0..127
            int cc = (c & 3) << 2;         // col {0,4,8,12}
            cp_async16(&As[s][r * LDA + cc], Ag + (size_t)r * Kd + k0 + cc);
            cp_async16(&Bs[s][r * LDA + cc], Bg + (size_t)r * Kd + k0 + cc);
        }
    };

    issue_tile(0, 0);
    cp_commit();

    for (int kt = 0; kt < nk; kt++) {
        const int s = kt & 1;
        if (kt + 1 < nk) {
            issue_tile((kt + 1) & 1, kt + 1);
            cp_commit();
            cp_wait<1>();
        } else {
            cp_wait<0>();
        }
        __syncthreads();

#pragma unroll
        for (int kk = 0; kk < 2; kk++) {
            const int k0 = kk * 8;
            // A fragments: 2 m-tiles x 4 regs
            uint32_t af[2][4];
#pragma unroll
            for (int mt = 0; mt < 2; mt++) {
                const float* ab = &As[s][(wm + mt * 16) * LDA + k0];
                af[mt][0] = f2tf32(ab[(g)     * LDA + t4]);
                af[mt][1] = f2tf32(ab[(g + 8) * LDA + t4]);
                af[mt][2] = f2tf32(ab[(g)     * LDA + t4 + 4]);
                af[mt][3] = f2tf32(ab[(g + 8) * LDA + t4 + 4]);
            }
#pragma unroll
            for (int nt = 0; nt < 8; nt++) {
                const float* bb = &Bs[s][(wn + nt * 8 + g) * LDA + k0];
                uint32_t b0 = f2tf32(bb[t4]);
                uint32_t b1 = f2tf32(bb[t4 + 4]);
#pragma unroll
                for (int mt = 0; mt < 2; mt++) {
                    asm volatile(
                        "mma.sync.aligned.m16n8k8.row.col.f32.tf32.tf32.f32 "
                        "{%0,%1,%2,%3}, {%4,%5,%6,%7}, {%8,%9}, {%0,%1,%2,%3};\n"
                        : "+f"(acc[mt][nt][0]), "+f"(acc[mt][nt][1]),
                          "+f"(acc[mt][nt][2]), "+f"(acc[mt][nt][3])
                        : "r"(af[mt][0]), "r"(af[mt][1]),
                          "r"(af[mt][2]), "r"(af[mt][3]),
                          "r"(b0), "r"(b1));
                }
            }
        }
        __syncthreads();
    }

    // Epilogue: bias + store (float2 per fragment row)
#pragma unroll
    for (int mt = 0; mt < 2; mt++) {
        const int row = by * BM + wm + mt * 16 + g;
#pragma unroll
        for (int nt = 0; nt < 8; nt++) {
            const int col = bx * BN + wn + nt * 8 + (t4 << 1);
            float bx0 = bias[col], bx1 = bias[col + 1];
            float2 v0, v1;
            v0.x = acc[mt][nt][0] + bx0; v0.y = acc[mt][nt][1] + bx1;
            v1.x = acc[mt][nt][2] + bx0; v1.y = acc[mt][nt][3] + bx1;
            *(float2*)(Cm + (size_t)row * Nd + col)       = v0;
            *(float2*)(Cm + (size_t)(row + 8) * Nd + col) = v1;
        }
    }
}

// ---------------------------------------------------------------------------
// Flash-style block-causal attention, fp32 (unchanged from R0 baseline).
// ---------------------------------------------------------------------------
__global__ __launch_bounds__(192, 2)
void attn_kernel(const float* __restrict__ qkv, float* __restrict__ attn_out)
{
    __shared__ float Ks[64][64];
    __shared__ float Vs[64][64];
    __shared__ int   kbi[64];
    __shared__ int   cmin[4];

    const int b   = blockIdx.z;
    const int h   = blockIdx.y;
    const int qt  = blockIdx.x;
    const int tid = threadIdx.x;
    const int qrow = qt * 192 + tid;

    const float* qptr = qkv + (size_t)(b * SEQ + qrow) * QKVC + h * HD;
    float q[HD];
#pragma unroll
    for (int d = 0; d < HD; d += 4)
        *(float4*)&q[d] = *(const float4*)(qptr + d);

    const int bq = block_idx_of(qrow);
    float m = -1e30f, l = 0.f;
    float o[HD];
#pragma unroll
    for (int d = 0; d < HD; d++) o[d] = 0.f;

    const float scale = 0.125f;

    for (int kt = 0; kt < SEQ / 64; kt++) {
        const float* kbase = qkv + (size_t)(b * SEQ + kt * 64) * QKVC + CH + h * HD;
        const float* vbase = kbase + CH;
        for (int u = tid; u < 64 * 16; u += 192) {
            int r = u >> 4, c = (u & 15) << 2;
            *(float4*)&Ks[r][c] = *(const float4*)(kbase + (size_t)r * QKVC + c);
            *(float4*)&Vs[r][c] = *(const float4*)(vbase + (size_t)r * QKVC + c);
        }
        if (tid < 64) kbi[tid] = block_idx_of(kt * 64 + tid);
        if (tid < 4) {
            int mn = 1 << 30;
#pragma unroll
            for (int jj = 0; jj < 16; jj++)
                mn = min(mn, block_idx_of(kt * 64 + tid * 16 + jj));
            cmin[tid] = mn;
        }
        __syncthreads();

        for (int c = 0; c < 4; c++) {
            if (cmin[c] > bq) continue;
            const int jb = c * 16;
            float s[16];
            float cmax = -1e30f;
#pragma unroll
            for (int j = 0; j < 16; j++) {
                if (kbi[jb + j] > bq) { s[j] = -1e30f; continue; }
                float a0 = 0.f, a1 = 0.f, a2 = 0.f, a3 = 0.f;
#pragma unroll
                for (int d = 0; d < HD; d += 4) {
                    a0 += q[d + 0] * Ks[jb + j][d + 0];
                    a1 += q[d + 1] * Ks[jb + j][d + 1];
                    a2 += q[d + 2] * Ks[jb + j][d + 2];
                    a3 += q[d + 3] * Ks[jb + j][d + 3];
                }
                float sv = ((a0 + a1) + (a2 + a3)) * scale;
                s[j] = sv;
                cmax = fmaxf(cmax, sv);
            }
            if (cmax < -1e29f) continue;

            float mnew = fmaxf(m, cmax);
            float corr = __expf(m - mnew);
            l *= corr;
#pragma unroll
            for (int d = 0; d < HD; d++) o[d] *= corr;

#pragma unroll
            for (int j = 0; j < 16; j++) {
                if (s[j] < -1e29f) continue;
                float p = __expf(s[j] - mnew);
                l += p;
#pragma unroll
                for (int d = 0; d < HD; d++)
                    o[d] += p * Vs[jb + j][d];
            }
            m = mnew;
        }
        __syncthreads();
    }

    const float inv = 1.f / l;
    float* optr = attn_out + (size_t)(b * SEQ + qrow) * CH + h * HD;
#pragma unroll
    for (int d = 0; d < HD; d += 4) {
        float4 v;
        v.x = o[d + 0] * inv; v.y = o[d + 1] * inv;
        v.z = o[d + 2] * inv; v.w = o[d + 3] * inv;
        *(float4*)(optr + d) = v;
    }
}

// ---------------------------------------------------------------------------
// Launch: tf32 qkv-GEMM -> attention -> tf32 proj-GEMM
// ---------------------------------------------------------------------------
extern "C" void kernel_launch(void* const* d_in, const int* in_sizes, int n_in,
                              void* d_out, int out_size)
{
    const float* x      = (const float*)d_in[0];
    const float* qkv_w  = (const float*)d_in[1];
    const float* qkv_b  = (const float*)d_in[2];
    const float* proj_w = (const float*)d_in[3];
    const float* proj_b = (const float*)d_in[4];
    float* out = (float*)d_out;

    float* qkvbuf = nullptr;
    float* attbuf = nullptr;
    cudaGetSymbolAddress((void**)&qkvbuf, g_qkv);
    cudaGetSymbolAddress((void**)&attbuf, g_att);

    // 1) qkv = x @ qkv_w^T + qkv_b : (18432, 2304), K=768
    dim3 g1(QKVC / 128, MROWS / 128);   // (18, 144)
    tf32_gemm_nt_bias<<<g1, 256>>>(x, qkv_w, qkv_b, qkvbuf, MROWS, QKVC, CH);

    // 2) block-causal attention -> (18432, 768)
    dim3 g2(SEQ / 192, NH, BATCH);      // (3, 12, 32)
    attn_kernel<<<g2, 192>>>(qkvbuf, attbuf);

    // 3) out = att @ proj_w^T + proj_b : (18432, 768), K=768
    dim3 g3(CH / 128, MROWS / 128);     // (6, 144)
    tf32_gemm_nt_bias<<<g3, 256>>>(attbuf, proj_w, proj_b, out, MROWS, CH, CH);
}

// round 3
// speedup vs baseline: 3.0652x; 1.4940x over previous
#include <cuda_runtime.h>
#include <cstdint>

// Problem constants
#define BATCH 32
#define SEQ   576
#define CH    768
#define NH    12
#define HD    64
#define MROWS (BATCH * SEQ)      // 18432
#define QKVC  (3 * CH)           // 2304
#define GRID24 24
#define BS4   4

// Scratch (allocation-free rule: __device__ globals)
__device__ float g_qkv[(size_t)MROWS * QKVC];   // (B*N, 3C)
__device__ float g_att[(size_t)MROWS * CH];     // (B*N, C)

__device__ __forceinline__ int block_idx_of(int p) {
    int i = p / GRID24;
    int j = p - i * GRID24;
    return (i >> 2) * (GRID24 / BS4) + (j >> 2);
}

// ---------------------------------------------------------------------------
// helpers
// ---------------------------------------------------------------------------
__device__ __forceinline__ void cp_async16(void* smem, const void* gmem) {
    uint32_t s = (uint32_t)__cvta_generic_to_shared(smem);
    asm volatile("cp.async.cg.shared.global [%0], [%1], 16;\n" :: "r"(s), "l"(gmem));
}
__device__ __forceinline__ void cp_commit() {
    asm volatile("cp.async.commit_group;\n");
}
template<int N>
__device__ __forceinline__ void cp_wait() {
    asm volatile("cp.async.wait_group %0;\n" :: "n"(N));
}
__device__ __forceinline__ uint32_t f2tf32(float f) {
    uint32_t u;
    asm("cvt.rna.tf32.f32 %0, %1;\n" : "=r"(u) : "f"(f));
    return u;
}

#define MMA_TF32(acc, a0,a1,a2,a3, b0,b1)                                      \
    asm volatile(                                                              \
        "mma.sync.aligned.m16n8k8.row.col.f32.tf32.tf32.f32 "                  \
        "{%0,%1,%2,%3}, {%4,%5,%6,%7}, {%8,%9}, {%0,%1,%2,%3};\n"              \
        : "+f"(acc[0]), "+f"(acc[1]), "+f"(acc[2]), "+f"(acc[3])               \
        : "r"(a0), "r"(a1), "r"(a2), "r"(a3), "r"(b0), "r"(b1))

// Fast exp on FMA pipe (deg-5 Taylor after range reduction, rel err ~2e-6).
__device__ __forceinline__ float fexp(float x) {
    x = fmaxf(x, -87.0f);
    float t = x * 1.44269504f;
    int   ei = __float2int_rn(t);
    float fn = (float)ei;
    float r  = fmaf(fn, -0.69314718f, x);
    float p  = 8.3333337e-3f;
    p = fmaf(p, r, 4.1666668e-2f);
    p = fmaf(p, r, 0.16666667f);
    p = fmaf(p, r, 0.5f);
    p = fmaf(p, r, 1.0f);
    p = fmaf(p, r, 1.0f);
    return p * __int_as_float((ei + 127) << 23);
}

// ---------------------------------------------------------------------------
// TF32 tensor-core GEMM (NT), unchanged from R1 (passing, 45% tensor).
// ---------------------------------------------------------------------------
__global__ __launch_bounds__(256)
void tf32_gemm_nt_bias(const float* __restrict__ A,
                       const float* __restrict__ Bm,
                       const float* __restrict__ bias,
                       float* __restrict__ Cm,
                       int Md, int Nd, int Kd)
{
    const int BM = 128, BN = 128, BK = 16;
    const int LDA = 20;
    __shared__ float As[2][BM * LDA];
    __shared__ float Bs[2][BN * LDA];

    const int tid  = threadIdx.x;
    const int wid  = tid >> 5;
    const int lane = tid & 31;
    const int g    = lane >> 2;
    const int t4   = lane & 3;
    const int wm   = (wid & 3) * 32;
    const int wn   = (wid >> 2) * 64;
    const int bx = blockIdx.x, by = blockIdx.y;

    const float* Ag = A  + (size_t)(by * BM) * Kd;
    const float* Bg = Bm + (size_t)(bx * BN) * Kd;

    float acc[2][8][4];
#pragma unroll
    for (int mt = 0; mt < 2; mt++)
#pragma unroll
        for (int nt = 0; nt < 8; nt++)
#pragma unroll
            for (int r = 0; r < 4; r++) acc[mt][nt][r] = 0.f;

    const int nk = Kd / BK;

    auto issue_tile = [&](int s, int kt) {
        const int k0 = kt * BK;
#pragma unroll
        for (int i = 0; i < 2; i++) {
            int c  = tid + (i << 8);
            int r  = c >> 2;
            int cc = (c & 3) << 2;
            cp_async16(&As[s][r * LDA + cc], Ag + (size_t)r * Kd + k0 + cc);
            cp_async16(&Bs[s][r * LDA + cc], Bg + (size_t)r * Kd + k0 + cc);
        }
    };

    issue_tile(0, 0);
    cp_commit();

    for (int kt = 0; kt < nk; kt++) {
        const int s = kt & 1;
        if (kt + 1 < nk) {
            issue_tile((kt + 1) & 1, kt + 1);
            cp_commit();
            cp_wait<1>();
        } else {
            cp_wait<0>();
        }
        __syncthreads();

#pragma unroll
        for (int kk = 0; kk < 2; kk++) {
            const int k0 = kk * 8;
            uint32_t af[2][4];
#pragma unroll
            for (int mt = 0; mt < 2; mt++) {
                const float* ab = &As[s][(wm + mt * 16) * LDA + k0];
                af[mt][0] = f2tf32(ab[(g)     * LDA + t4]);
                af[mt][1] = f2tf32(ab[(g + 8) * LDA + t4]);
                af[mt][2] = f2tf32(ab[(g)     * LDA + t4 + 4]);
                af[mt][3] = f2tf32(ab[(g + 8) * LDA + t4 + 4]);
            }
#pragma unroll
            for (int nt = 0; nt < 8; nt++) {
                const float* bb = &Bs[s][(wn + nt * 8 + g) * LDA + k0];
                uint32_t b0 = f2tf32(bb[t4]);
                uint32_t b1 = f2tf32(bb[t4 + 4]);
#pragma unroll
                for (int mt = 0; mt < 2; mt++) {
                    MMA_TF32(acc[mt][nt], af[mt][0], af[mt][1], af[mt][2], af[mt][3], b0, b1);
                }
            }
        }
        __syncthreads();
    }

#pragma unroll
    for (int mt = 0; mt < 2; mt++) {
        const int row = by * BM + wm + mt * 16 + g;
#pragma unroll
        for (int nt = 0; nt < 8; nt++) {
            const int col = bx * BN + wn + nt * 8 + (t4 << 1);
            float bx0 = bias[col], bx1 = bias[col + 1];
            float2 v0, v1;
            v0.x = acc[mt][nt][0] + bx0; v0.y = acc[mt][nt][1] + bx1;
            v1.x = acc[mt][nt][2] + bx0; v1.y = acc[mt][nt][3] + bx1;
            *(float2*)(Cm + (size_t)row * Nd + col)       = v0;
            *(float2*)(Cm + (size_t)(row + 8) * Nd + col) = v1;
        }
    }
}

// ---------------------------------------------------------------------------
// Tensor-core block-causal flash attention.
// Block = (qt, h, b): 64 q-rows, 4 warps (16 rows each). K-tiles of 64 keys.
// QK^T: 3x tf32 split-mma (fp32-accurate scores). Softmax: poly exp.
// PV: single tf32 mma, P roundtrip through smem.
// ---------------------------------------------------------------------------
#define LDSA 68   // padded smem row stride (floats): conflict-free fragments

struct AttnSmem {
    float Ksb[64 * LDSA];   // K big (tf32-valued floats)
    float Kss[64 * LDSA];   // K small
    float Vt [64 * LDSA];   // V (tf32-valued floats)
    float Ps [64 * LDSA];   // P tile
    int   kbi[SEQ];
    int   kmin[9];
    int   maxbq;
};

__global__ __launch_bounds__(128)
void attn_tc(const float* __restrict__ qkv, float* __restrict__ att)
{
    extern __shared__ char smraw[];
    AttnSmem& sm = *reinterpret_cast<AttnSmem*>(smraw);

    const int b = blockIdx.z, h = blockIdx.y, qt = blockIdx.x;
    const int tid = threadIdx.x, wid = tid >> 5, lane = tid & 31;
    const int g = lane >> 2, t4 = lane & 3;
    const int wm = wid * 16;

    // Startup: block-index table + per-tile mins + q-tile max
    for (int p = tid; p < SEQ; p += 128) sm.kbi[p] = block_idx_of(p);
    __syncthreads();
    if (tid < 9) {
        int mn = 1 << 30;
        for (int j = 0; j < 64; j++) mn = min(mn, sm.kbi[tid * 64 + j]);
        sm.kmin[tid] = mn;
    } else if (tid == 9) {
        int mx = -1;
        for (int j = 0; j < 64; j++) mx = max(mx, sm.kbi[qt * 64 + j]);
        sm.maxbq = mx;
    }
    __syncthreads();

    const int qr0 = qt * 64 + wm + g;         // this lane's row 0 (row 1 = +8)
    const int bq0 = sm.kbi[qr0];
    const int bq1 = sm.kbi[qr0 + 8];
    const int maxbq = sm.maxbq;

    // Q fragments in registers, pre-scaled by 1/8, split big/small
    uint32_t qb[8][4], qs[8][4];
    {
        const float* Qp0 = qkv + (size_t)(b * SEQ + qr0) * QKVC + h * HD;
        const float* Qp1 = Qp0 + (size_t)8 * QKVC;
#pragma unroll
        for (int kk = 0; kk < 8; kk++) {
            float r0 = Qp0[kk * 8 + t4]     * 0.125f;
            float r1 = Qp1[kk * 8 + t4]     * 0.125f;
            float r2 = Qp0[kk * 8 + t4 + 4] * 0.125f;
            float r3 = Qp1[kk * 8 + t4 + 4] * 0.125f;
            qb[kk][0] = f2tf32(r0); qs[kk][0] = f2tf32(r0 - __uint_as_float(qb[kk][0]));
            qb[kk][1] = f2tf32(r1); qs[kk][1] = f2tf32(r1 - __uint_as_float(qb[kk][1]));
            qb[kk][2] = f2tf32(r2); qs[kk][2] = f2tf32(r2 - __uint_as_float(qb[kk][2]));
            qb[kk][3] = f2tf32(r3); qs[kk][3] = f2tf32(r3 - __uint_as_float(qb[kk][3]));
        }
    }

    float m0 = -1e30f, m1 = -1e30f, l0 = 0.f, l1 = 0.f;
    float o[8][4];
#pragma unroll
    for (int nt = 0; nt < 8; nt++)
#pragma unroll
        for (int r = 0; r < 4; r++) o[nt][r] = 0.f;

    for (int kt = 0; kt < 9; kt++) {
        if (sm.kmin[kt] > maxbq) continue;        // uniform per block
        __syncthreads();                           // protect smem reuse

        // Load K (split big/small) and V (tf32-rounded) tiles
        {
            const float* Kg = qkv + (size_t)(b * SEQ + kt * 64) * QKVC + CH + h * HD;
            const float* Vg = Kg + CH;
#pragma unroll
            for (int i = 0; i < 8; i++) {
                int u = tid + i * 128;
                int r = u >> 4, c = (u & 15) << 2;
                float4 k4 = *(const float4*)(Kg + (size_t)r * QKVC + c);
                float4 v4 = *(const float4*)(Vg + (size_t)r * QKVC + c);
                uint32_t kb0 = f2tf32(k4.x), kb1 = f2tf32(k4.y);
                uint32_t kb2 = f2tf32(k4.z), kb3 = f2tf32(k4.w);
                float4 big, sml, vt;
                big.x = __uint_as_float(kb0); big.y = __uint_as_float(kb1);
                big.z = __uint_as_float(kb2); big.w = __uint_as_float(kb3);
                sml.x = __uint_as_float(f2tf32(k4.x - big.x));
                sml.y = __uint_as_float(f2tf32(k4.y - big.y));
                sml.z = __uint_as_float(f2tf32(k4.z - big.z));
                sml.w = __uint_as_float(f2tf32(k4.w - big.w));
                vt.x = __uint_as_float(f2tf32(v4.x));
                vt.y = __uint_as_float(f2tf32(v4.y));
                vt.z = __uint_as_float(f2tf32(v4.z));
                vt.w = __uint_as_float(f2tf32(v4.w));
                *(float4*)&sm.Ksb[r * LDSA + c] = big;
                *(float4*)&sm.Kss[r * LDSA + c] = sml;
                *(float4*)&sm.Vt [r * LDSA + c] = vt;
            }
        }
        __syncthreads();

        // S = Q K^T (3x tf32 split)
        float sacc[8][4];
#pragma unroll
        for (int nt = 0; nt < 8; nt++)
#pragma unroll
            for (int r = 0; r < 4; r++) sacc[nt][r] = 0.f;

#pragma unroll
        for (int kk = 0; kk < 8; kk++) {
#pragma unroll
            for (int nt = 0; nt < 8; nt++) {
                const float* kbp = &sm.Ksb[(nt * 8 + g) * LDSA + kk * 8];
                const float* ksp = &sm.Kss[(nt * 8 + g) * LDSA + kk * 8];
                uint32_t bb0 = __float_as_uint(kbp[t4]);
                uint32_t bb1 = __float_as_uint(kbp[t4 + 4]);
                uint32_t bs0 = __float_as_uint(ksp[t4]);
                uint32_t bs1 = __float_as_uint(ksp[t4 + 4]);
                MMA_TF32(sacc[nt], qb[kk][0], qb[kk][1], qb[kk][2], qb[kk][3], bb0, bb1);
                MMA_TF32(sacc[nt], qb[kk][0], qb[kk][1], qb[kk][2], qb[kk][3], bs0, bs1);
                MMA_TF32(sacc[nt], qs[kk][0], qs[kk][1], qs[kk][2], qs[kk][3], bb0, bb1);
            }
        }

        // Mask
        const int c0 = kt * 64;
        int kbl[16];
#pragma unroll
        for (int nt = 0; nt < 8; nt++) {
            kbl[nt * 2]     = sm.kbi[c0 + nt * 8 + 2 * t4];
            kbl[nt * 2 + 1] = sm.kbi[c0 + nt * 8 + 2 * t4 + 1];
        }
#pragma unroll
        for (int nt = 0; nt < 8; nt++) {
            if (kbl[nt * 2]     > bq0) sacc[nt][0] = -1e30f;
            if (kbl[nt * 2 + 1] > bq0) sacc[nt][1] = -1e30f;
            if (kbl[nt * 2]     > bq1) sacc[nt][2] = -1e30f;
            if (kbl[nt * 2 + 1] > bq1) sacc[nt][3] = -1e30f;
        }

        // Row max (reduce over the 4 lanes of the t4 group)
        float mx0 = -1e30f, mx1 = -1e30f;
#pragma unroll
        for (int nt = 0; nt < 8; nt++) {
            mx0 = fmaxf(mx0, fmaxf(sacc[nt][0], sacc[nt][1]));
            mx1 = fmaxf(mx1, fmaxf(sacc[nt][2], sacc[nt][3]));
        }
        mx0 = fmaxf(mx0, __shfl_xor_sync(0xffffffffu, mx0, 1));
        mx0 = fmaxf(mx0, __shfl_xor_sync(0xffffffffu, mx0, 2));
        mx1 = fmaxf(mx1, __shfl_xor_sync(0xffffffffu, mx1, 1));
        mx1 = fmaxf(mx1, __shfl_xor_sync(0xffffffffu, mx1, 2));

        float nm0 = fmaxf(m0, mx0), nm1 = fmaxf(m1, mx1);
        float cr0 = fexp(m0 - nm0), cr1 = fexp(m1 - nm1);
        m0 = nm0; m1 = nm1;
        l0 *= cr0; l1 *= cr1;
#pragma unroll
        for (int nt = 0; nt < 8; nt++) {
            o[nt][0] *= cr0; o[nt][1] *= cr0;
            o[nt][2] *= cr1; o[nt][3] *= cr1;
        }

        // p = exp(s - m), tf32-rounded (so l matches PV numerator exactly)
        float s0 = 0.f, s1 = 0.f;
        float* pr0 = &sm.Ps[(size_t)(wm + g) * LDSA];
        float* pr1 = &sm.Ps[(size_t)(wm + g + 8) * LDSA];
#pragma unroll
        for (int nt = 0; nt < 8; nt++) {
            float p0 = (sacc[nt][0] > -1e29f) ? fexp(sacc[nt][0] - nm0) : 0.f;
            float p1 = (sacc[nt][1] > -1e29f) ? fexp(sacc[nt][1] - nm0) : 0.f;
            float p2 = (sacc[nt][2] > -1e29f) ? fexp(sacc[nt][2] - nm1) : 0.f;
            float p3 = (sacc[nt][3] > -1e29f) ? fexp(sacc[nt][3] - nm1) : 0.f;
            p0 = __uint_as_float(f2tf32(p0));
            p1 = __uint_as_float(f2tf32(p1));
            p2 = __uint_as_float(f2tf32(p2));
            p3 = __uint_as_float(f2tf32(p3));
            s0 += p0 + p1; s1 += p2 + p3;
            float2 w0; w0.x = p0; w0.y = p1;
            float2 w1; w1.x = p2; w1.y = p3;
            *(float2*)(pr0 + nt * 8 + 2 * t4) = w0;
            *(float2*)(pr1 + nt * 8 + 2 * t4) = w1;
        }
        s0 += __shfl_xor_sync(0xffffffffu, s0, 1);
        s0 += __shfl_xor_sync(0xffffffffu, s0, 2);
        s1 += __shfl_xor_sync(0xffffffffu, s1, 1);
        s1 += __shfl_xor_sync(0xffffffffu, s1, 2);
        l0 += s0; l1 += s1;
        __syncwarp();

        // O += P @ V
#pragma unroll
        for (int kk = 0; kk < 8; kk++) {
            uint32_t a0 = __float_as_uint(sm.Ps[(wm + g) * LDSA + kk * 8 + t4]);
            uint32_t a1 = __float_as_uint(sm.Ps[(wm + g + 8) * LDSA + kk * 8 + t4]);
            uint32_t a2 = __float_as_uint(sm.Ps[(wm + g) * LDSA + kk * 8 + t4 + 4]);
            uint32_t a3 = __float_as_uint(sm.Ps[(wm + g + 8) * LDSA + kk * 8 + t4 + 4]);
#pragma unroll
            for (int nt = 0; nt < 8; nt++) {
                uint32_t b0v = __float_as_uint(sm.Vt[(kk * 8 + t4) * LDSA + nt * 8 + g]);
                uint32_t b1v = __float_as_uint(sm.Vt[(kk * 8 + t4 + 4) * LDSA + nt * 8 + g]);
                MMA_TF32(o[nt], a0, a1, a2, a3, b0v, b1v);
            }
        }
        __syncwarp();
    }

    // Normalize + store
    const float inv0 = 1.f / l0, inv1 = 1.f / l1;
    float* Or0 = att + (size_t)(b * SEQ + qr0) * CH + h * HD;
    float* Or1 = Or0 + (size_t)8 * CH;
#pragma unroll
    for (int nt = 0; nt < 8; nt++) {
        float2 v0, v1;
        v0.x = o[nt][0] * inv0; v0.y = o[nt][1] * inv0;
        v1.x = o[nt][2] * inv1; v1.y = o[nt][3] * inv1;
        *(float2*)(Or0 + nt * 8 + 2 * t4) = v0;
        *(float2*)(Or1 + nt * 8 + 2 * t4) = v1;
    }
}

// ---------------------------------------------------------------------------
// Launch
// ---------------------------------------------------------------------------
extern "C" void kernel_launch(void* const* d_in, const int* in_sizes, int n_in,
                              void* d_out, int out_size)
{
    const float* x      = (const float*)d_in[0];
    const float* qkv_w  = (const float*)d_in[1];
    const float* qkv_b  = (const float*)d_in[2];
    const float* proj_w = (const float*)d_in[3];
    const float* proj_b = (const float*)d_in[4];
    float* out = (float*)d_out;

    float* qkvbuf = nullptr;
    float* attbuf = nullptr;
    cudaGetSymbolAddress((void**)&qkvbuf, g_qkv);
    cudaGetSymbolAddress((void**)&attbuf, g_att);

    const int attn_smem = (int)sizeof(AttnSmem);
    cudaFuncSetAttribute(attn_tc, cudaFuncAttributeMaxDynamicSharedMemorySize, attn_smem);

    // 1) qkv = x @ qkv_w^T + qkv_b
    dim3 g1(QKVC / 128, MROWS / 128);
    tf32_gemm_nt_bias<<<g1, 256>>>(x, qkv_w, qkv_b, qkvbuf, MROWS, QKVC, CH);

    // 2) tensor-core block-causal attention
    dim3 g2(SEQ / 64, NH, BATCH);     // (9, 12, 32)
    attn_tc<<<g2, 128, attn_smem>>>(qkvbuf, attbuf);

    // 3) out = att @ proj_w^T + proj_b
    dim3 g3(CH / 128, MROWS / 128);
    tf32_gemm_nt_bias<<<g3, 256>>>(attbuf, proj_w, proj_b, out, MROWS, CH, CH);
}